// round 13
// baseline (speedup 1.0000x reference)
#include <cuda_runtime.h>

#define N 8192
#define RANK 4
#define SCALING 2.0f   // ALPHA / RANK = 8 / 4
#define EPS 1e-5f
#define TPB 512
#define VPT 4              // float4 slots per thread per row
#define ROWS_TOTAL 8192
#define ROW_STRIDE (ROWS_TOTAL / 2)   // second row = bid + 4096

// Allocation-free scratch for the adapted affine vectors.
__device__ float g_scale[N];
__device__ float g_shift[N];

// ---------------------------------------------------------------------------
// Kernel 1: rank-4 low-rank diagonal -> per-feature scale/shift vectors.
// ---------------------------------------------------------------------------
__global__ void lora_vectors_kernel(const float* __restrict__ sA,
                                    const float* __restrict__ sB,
                                    const float* __restrict__ hA,
                                    const float* __restrict__ hB) {
    int i = blockIdx.x * blockDim.x + threadIdx.x;
    if (i >= N) return;
    float4 a_s = *(const float4*)(sA + i * RANK);
    float4 a_h = *(const float4*)(hA + i * RANK);
    float s = a_s.x * sB[0 * N + i] + a_s.y * sB[1 * N + i]
            + a_s.z * sB[2 * N + i] + a_s.w * sB[3 * N + i];
    float h = a_h.x * hB[0 * N + i] + a_h.y * hB[1 * N + i]
            + a_h.z * hB[2 * N + i] + a_h.w * hB[3 * N + i];
    g_scale[i] = s * SCALING;
    g_shift[i] = h * SCALING;
}

// ---------------------------------------------------------------------------
// Kernel 2: fused LayerNorm, TWO rows per CTA (bid and bid+4096).
//  - 8 front-batched streaming float4 loads per thread (MLP=8)
//  - ONE barrier serves both rows' reductions
//  - scale/shift loaded once per thread-slot, reused for both rows
//  - __launch_bounds__(512, 2): regs capped at 64, 2 CTAs/SM
// ---------------------------------------------------------------------------
__global__ __launch_bounds__(TPB, 2) void lora_ln_kernel(const float* __restrict__ x,
                                                         float* __restrict__ out) {
    const int t = threadIdx.x;
    const int lane = t & 31, warp = t >> 5;
    const size_t off0 = (size_t)blockIdx.x * N;
    const size_t off1 = (size_t)(blockIdx.x + ROW_STRIDE) * N;
    const float4* __restrict__ xr0 = (const float4*)(x + off0);
    const float4* __restrict__ xr1 = (const float4*)(x + off1);
    float4* __restrict__ yr0 = (float4*)(out + off0);
    float4* __restrict__ yr1 = (float4*)(out + off1);

    // Front-batched streaming loads: both rows, 8 independent LDG.128.
    float4 v0[VPT], v1[VPT];
#pragma unroll
    for (int i = 0; i < VPT; i++) v0[i] = __ldcs(xr0 + t + i * TPB);
#pragma unroll
    for (int i = 0; i < VPT; i++) v1[i] = __ldcs(xr1 + t + i * TPB);

    float sum0 = 0.f, sq0 = 0.f, sum1 = 0.f, sq1 = 0.f;
#pragma unroll
    for (int i = 0; i < VPT; i++) {
        sum0 += v0[i].x + v0[i].y + v0[i].z + v0[i].w;
        sq0  += v0[i].x * v0[i].x + v0[i].y * v0[i].y
              + v0[i].z * v0[i].z + v0[i].w * v0[i].w;
        sum1 += v1[i].x + v1[i].y + v1[i].z + v1[i].w;
        sq1  += v1[i].x * v1[i].x + v1[i].y * v1[i].y
              + v1[i].z * v1[i].z + v1[i].w * v1[i].w;
    }

#pragma unroll
    for (int off = 16; off > 0; off >>= 1) {
        sum0 += __shfl_xor_sync(0xFFFFFFFFu, sum0, off);
        sq0  += __shfl_xor_sync(0xFFFFFFFFu, sq0,  off);
        sum1 += __shfl_xor_sync(0xFFFFFFFFu, sum1, off);
        sq1  += __shfl_xor_sync(0xFFFFFFFFu, sq1,  off);
    }

    // ONE barrier: publish both rows' warp partials, then every warp folds.
    __shared__ float4 s_part[16];   // (sum0, sq0, sum1, sq1) per warp
    if (lane == 0) s_part[warp] = make_float4(sum0, sq0, sum1, sq1);
    __syncthreads();

    float4 p = s_part[lane & 15];
#pragma unroll
    for (int off = 8; off > 0; off >>= 1) {
        p.x += __shfl_xor_sync(0xFFFFFFFFu, p.x, off);
        p.y += __shfl_xor_sync(0xFFFFFFFFu, p.y, off);
        p.z += __shfl_xor_sync(0xFFFFFFFFu, p.z, off);
        p.w += __shfl_xor_sync(0xFFFFFFFFu, p.w, off);
    }
    const float mean0 = p.x * (1.0f / N);
    const float rstd0 = rsqrtf(p.y * (1.0f / N) - mean0 * mean0 + EPS);
    const float mean1 = p.z * (1.0f / N);
    const float rstd1 = rsqrtf(p.w * (1.0f / N) - mean1 * mean1 + EPS);

    // Epilogue: sc/sh loaded once per slot, used for BOTH rows.
    // o = v*a + b with a = rstd*sc, b = sh - mean*a.
    const float4* __restrict__ sc = (const float4*)g_scale;
    const float4* __restrict__ sh = (const float4*)g_shift;
#pragma unroll
    for (int i = 0; i < VPT; i++) {
        const int idx = t + i * TPB;
        float4 s = sc[idx];
        float4 h = sh[idx];
        float4 a, b, o;

        a.x = rstd0 * s.x; a.y = rstd0 * s.y; a.z = rstd0 * s.z; a.w = rstd0 * s.w;
        b.x = h.x - mean0 * a.x; b.y = h.y - mean0 * a.y;
        b.z = h.z - mean0 * a.z; b.w = h.w - mean0 * a.w;
        o.x = v0[i].x * a.x + b.x; o.y = v0[i].y * a.y + b.y;
        o.z = v0[i].z * a.z + b.z; o.w = v0[i].w * a.w + b.w;
        __stcs(yr0 + idx, o);

        a.x = rstd1 * s.x; a.y = rstd1 * s.y; a.z = rstd1 * s.z; a.w = rstd1 * s.w;
        b.x = h.x - mean1 * a.x; b.y = h.y - mean1 * a.y;
        b.z = h.z - mean1 * a.z; b.w = h.w - mean1 * a.w;
        o.x = v1[i].x * a.x + b.x; o.y = v1[i].y * a.y + b.y;
        o.z = v1[i].z * a.z + b.z; o.w = v1[i].w * a.w + b.w;
        __stcs(yr1 + idx, o);
    }
}

extern "C" void kernel_launch(void* const* d_in, const int* in_sizes, int n_in,
                              void* d_out, int out_size) {
    const float* x  = (const float*)d_in[0];
    const float* sA = (const float*)d_in[1];
    const float* sB = (const float*)d_in[2];
    const float* hA = (const float*)d_in[3];
    const float* hB = (const float*)d_in[4];
    float* out = (float*)d_out;

    const int rows = out_size / N;        // 8192
    const int grid = rows / 2;            // 4096 CTAs, 2 rows each

    lora_vectors_kernel<<<128, 64>>>(sA, sB, hA, hB);
    lora_ln_kernel<<<grid, TPB>>>(x, out);
}